// round 4
// baseline (speedup 1.0000x reference)
#include <cuda_runtime.h>

#define N_NODES 100000
#define N_EDGES 600000
#define E_TOT   700000      // edges + self loops
#define D       128
#define SCAN_B  1024
#define NB      ((N_NODES + SCAN_B - 1) / SCAN_B)   // 98
#define MEAN_B  256

// ---------------- scratch: __device__ globals only (no allocations) ----------------
__device__ __align__(16) float g_h[(size_t)N_NODES * D];   // post-GEMM features
__device__ __align__(16) float g_o[(size_t)N_NODES * D];   // layer output
__device__ float g_as[N_NODES];
__device__ float g_ad[N_NODES];
__device__ int   g_deg[N_NODES];
__device__ int   g_incl[N_NODES];
__device__ int   g_bsum[NB];
__device__ int   g_bpre[NB];
__device__ int   g_rp[N_NODES + 1];   // CSR row_ptr (by dst)
__device__ int   g_cur[N_NODES];      // scatter cursor
__device__ int   g_col[E_TOT];        // src node per incoming edge
__device__ float g_part[MEAN_B * D];

// ---------------- CSR build (edge_index is int32: [src x E | dst x E]) ------------
__global__ void k_deg_init() {
    int i = blockIdx.x * blockDim.x + threadIdx.x;
    if (i < N_NODES) g_deg[i] = 1;   // self loop
}

__global__ void k_deg_count(const int* __restrict__ ei) {
    int e = blockIdx.x * blockDim.x + threadIdx.x;
    if (e < N_EDGES) {
        int d = ei[N_EDGES + e];
        if ((unsigned)d < N_NODES) atomicAdd(&g_deg[d], 1);
    }
}

__global__ void __launch_bounds__(SCAN_B) k_scan1() {
    __shared__ int s[SCAN_B];
    int tl = threadIdx.x;
    int t  = blockIdx.x * SCAN_B + tl;
    int v  = (t < N_NODES) ? g_deg[t] : 0;
    s[tl] = v;
    __syncthreads();
    #pragma unroll
    for (int off = 1; off < SCAN_B; off <<= 1) {
        int add = (tl >= off) ? s[tl - off] : 0;
        __syncthreads();
        s[tl] += add;
        __syncthreads();
    }
    if (t < N_NODES) g_incl[t] = s[tl];
    if (tl == SCAN_B - 1) g_bsum[blockIdx.x] = s[tl];
}

__global__ void k_scan2() {
    __shared__ int s[128];
    int t = threadIdx.x;
    int v = (t < NB) ? g_bsum[t] : 0;
    s[t] = v;
    __syncthreads();
    #pragma unroll
    for (int off = 1; off < 128; off <<= 1) {
        int add = (t >= off) ? s[t - off] : 0;
        __syncthreads();
        s[t] += add;
        __syncthreads();
    }
    if (t < NB) g_bpre[t] = s[t] - v;   // exclusive prefix of block sums
}

__global__ void k_scan3() {
    int t = blockIdx.x * blockDim.x + threadIdx.x;
    if (t < N_NODES) {
        int S = g_incl[t] + g_bpre[t / SCAN_B];   // inclusive prefix
        g_rp[t + 1] = S;
        g_cur[t]    = S - g_deg[t];
        if (t == 0) g_rp[0] = 0;
    }
}

__global__ void k_scatter(const int* __restrict__ ei) {
    int e = blockIdx.x * blockDim.x + threadIdx.x;
    if (e >= E_TOT) return;
    int s, d;
    if (e < N_EDGES) { s = ei[e]; d = ei[N_EDGES + e]; }
    else             { s = e - N_EDGES; d = s; }
    if ((unsigned)s >= N_NODES || (unsigned)d >= N_NODES) return;
    int pos = atomicAdd(&g_cur[d], 1);
    g_col[pos] = s;
}

// ---------------- GEMM: g_h = X*W, g_as = h.a_src, g_ad = h.a_dst ----------------
// 256 thr, 64 rows x 128 cols; static smem: Xs 32KB + Wc 8KB = 40KB
__global__ void __launch_bounds__(256) k_gemm(
    const float* __restrict__ Xext, int use_ext,
    const float* __restrict__ W,
    const float* __restrict__ avs, const float* __restrict__ avd)
{
    __shared__ float Xs[64 * D];      // 64 rows x 128
    __shared__ float Wc[16 * D];      // k-chunk 16 x 128

    const float* X = use_ext ? Xext : g_o;
    const int tid  = threadIdx.x;
    const int row0 = blockIdx.x * 64;

    // stage X tile once
    {
        float4* Xs4 = (float4*)Xs;
        const float4* X4 = (const float4*)X;
        #pragma unroll
        for (int i = tid; i < 64 * D / 4; i += 256) {
            int r  = i / (D / 4);
            int gr = row0 + r;
            Xs4[i] = (gr < N_NODES) ? X4[(size_t)gr * (D / 4) + (i % (D / 4))]
                                    : make_float4(0.f, 0.f, 0.f, 0.f);
        }
    }

    const int warp  = tid >> 5;
    const int lane  = tid & 31;
    const int rbase = warp * 8;
    const int c0    = lane * 4;

    float acc[8][4];
    #pragma unroll
    for (int i = 0; i < 8; i++)
        #pragma unroll
        for (int j = 0; j < 4; j++) acc[i][j] = 0.f;

    for (int kc = 0; kc < D / 16; kc++) {
        __syncthreads();
        // load W chunk rows [kc*16, kc*16+16)
        {
            float4* Wc4 = (float4*)Wc;
            const float4* W4 = (const float4*)W + (size_t)kc * 16 * (D / 4);
            #pragma unroll
            for (int i = tid; i < 16 * D / 4; i += 256) Wc4[i] = W4[i];
        }
        __syncthreads();

        #pragma unroll
        for (int k = 0; k < 16; k++) {
            float4 wv = *(const float4*)&Wc[k * D + c0];
            int kg = kc * 16 + k;
            #pragma unroll
            for (int i = 0; i < 8; i++) {
                float xv = Xs[(rbase + i) * D + kg];
                acc[i][0] = fmaf(xv, wv.x, acc[i][0]);
                acc[i][1] = fmaf(xv, wv.y, acc[i][1]);
                acc[i][2] = fmaf(xv, wv.z, acc[i][2]);
                acc[i][3] = fmaf(xv, wv.w, acc[i][3]);
            }
        }
    }

    const float4 as4 = *(const float4*)&avs[c0];
    const float4 ad4 = *(const float4*)&avd[c0];

    #pragma unroll
    for (int i = 0; i < 8; i++) {
        int gr = row0 + rbase + i;
        if (gr < N_NODES) {
            *(float4*)&g_h[(size_t)gr * D + c0] =
                make_float4(acc[i][0], acc[i][1], acc[i][2], acc[i][3]);
        }
        float ps = acc[i][0]*as4.x + acc[i][1]*as4.y + acc[i][2]*as4.z + acc[i][3]*as4.w;
        float pd = acc[i][0]*ad4.x + acc[i][1]*ad4.y + acc[i][2]*ad4.z + acc[i][3]*ad4.w;
        #pragma unroll
        for (int off = 16; off; off >>= 1) {
            ps += __shfl_xor_sync(0xffffffffu, ps, off);
            pd += __shfl_xor_sync(0xffffffffu, pd, off);
        }
        if (lane == 0 && gr < N_NODES) { g_as[gr] = ps; g_ad[gr] = pd; }
    }
}

// ---------------- warp-per-node softmax + aggregation (no atomics) ----------------
__device__ __forceinline__ float leaky02(float e) {
    return fmaxf(e, 0.f) + 0.2f * fminf(e, 0.f);
}

__global__ void __launch_bounds__(256) k_node_agg(int do_relu, const float* __restrict__ b)
{
    int node = (blockIdx.x * blockDim.x + threadIdx.x) >> 5;
    int lane = threadIdx.x & 31;
    if (node >= N_NODES) return;

    int beg = g_rp[node];
    int end = g_rp[node + 1];
    float ad = g_ad[node];

    // pass 1: max
    float mx = -3.4e38f;
    for (int j = beg + lane; j < end; j += 32)
        mx = fmaxf(mx, leaky02(g_as[g_col[j]] + ad));
    #pragma unroll
    for (int off = 16; off; off >>= 1)
        mx = fmaxf(mx, __shfl_xor_sync(0xffffffffu, mx, off));

    // pass 2: denom
    float den = 0.f;
    for (int j = beg + lane; j < end; j += 32)
        den += __expf(leaky02(g_as[g_col[j]] + ad) - mx);
    #pragma unroll
    for (int off = 16; off; off >>= 1)
        den += __shfl_xor_sync(0xffffffffu, den, off);
    float inv = 1.f / den;

    // pass 3: feature accumulate (lane owns 4 columns)
    float4 acc = make_float4(0.f, 0.f, 0.f, 0.f);
    for (int j = beg; j < end; j++) {
        int s = g_col[j];                          // warp-uniform broadcast
        float w = __expf(leaky02(g_as[s] + ad) - mx) * inv;
        float4 hv = *(const float4*)&g_h[(size_t)s * D + lane * 4];
        acc.x = fmaf(w, hv.x, acc.x);
        acc.y = fmaf(w, hv.y, acc.y);
        acc.z = fmaf(w, hv.z, acc.z);
        acc.w = fmaf(w, hv.w, acc.w);
    }

    const float4 b4 = *(const float4*)&b[lane * 4];
    acc.x += b4.x; acc.y += b4.y; acc.z += b4.z; acc.w += b4.w;
    if (do_relu) {
        acc.x = fmaxf(acc.x, 0.f); acc.y = fmaxf(acc.y, 0.f);
        acc.z = fmaxf(acc.z, 0.f); acc.w = fmaxf(acc.w, 0.f);
    }
    *(float4*)&g_o[(size_t)node * D + lane * 4] = acc;
}

// ---------------- mean over nodes ----------------
__global__ void k_mean1() {
    int c = threadIdx.x;   // 128 threads = 128 cols
    float acc = 0.f;
    for (int r = blockIdx.x; r < N_NODES; r += MEAN_B)
        acc += g_o[(size_t)r * D + c];
    g_part[blockIdx.x * D + c] = acc;
}

__global__ void k_mean2(float* __restrict__ out) {
    int c = threadIdx.x;
    float s = 0.f;
    for (int i = 0; i < MEAN_B; i++) s += g_part[i * D + c];
    out[c] = s * (1.0f / N_NODES);
}

// ---------------- driver: kernel launches ONLY ----------------
extern "C" void kernel_launch(void* const* d_in, const int* in_sizes, int n_in,
                              void* d_out, int out_size)
{
    const float* x   = (const float*)d_in[0];
    const int*   ei  = (const int*)d_in[1];      // int32! [src x E | dst x E]
    const float* W1  = (const float*)d_in[2];
    const float* as1 = (const float*)d_in[3];
    const float* ad1 = (const float*)d_in[4];
    const float* b1  = (const float*)d_in[5];
    const float* W2  = (const float*)d_in[6];
    const float* as2 = (const float*)d_in[7];
    const float* ad2 = (const float*)d_in[8];
    const float* b2  = (const float*)d_in[9];
    float* out = (float*)d_out;

    // CSR build (identical for both layers)
    k_deg_init <<<(N_NODES + 255) / 256, 256>>>();
    k_deg_count<<<(N_EDGES + 255) / 256, 256>>>(ei);
    k_scan1    <<<NB, SCAN_B>>>();
    k_scan2    <<<1, 128>>>();
    k_scan3    <<<(N_NODES + 255) / 256, 256>>>();
    k_scatter  <<<(E_TOT + 255) / 256, 256>>>(ei);

    // layer 1: x -> g_h -> g_o (relu)
    k_gemm    <<<(N_NODES + 63) / 64, 256>>>(x, 1, W1, as1, ad1);
    k_node_agg<<<(N_NODES * 32 + 255) / 256, 256>>>(1, b1);

    // layer 2: g_o -> g_h -> g_o
    k_gemm    <<<(N_NODES + 63) / 64, 256>>>(nullptr, 0, W2, as2, ad2);
    k_node_agg<<<(N_NODES * 32 + 255) / 256, 256>>>(0, b2);

    // mean over nodes -> d_out[128]
    k_mean1<<<MEAN_B, D>>>();
    k_mean2<<<1, D>>>(out);
}